// round 6
// baseline (speedup 1.0000x reference)
#include <cuda_runtime.h>
#include <cuda_bf16.h>
#include <cstdint>

#define MAX_N 100000
#define MAX_E 1600000
#define HID   64
#define SCAN_TILE 1024
#define MAX_BLKS  ((MAX_N + SCAN_TILE - 1) / SCAN_TILE)

// Scratch: __device__ globals, referenced directly by symbol in device code.
__device__ __align__(16) float g_bufA[MAX_N * HID];
__device__ __align__(16) float g_bufB[MAX_N * HID];
__device__ float g_dis[MAX_N];
__device__ int   g_hist[MAX_N];      // edge in-degree (no self-loop)
__device__ int   g_rowptr[MAX_N];
__device__ int   g_cursor[MAX_N];
__device__ int   g_uhist[MAX_N];     // user_idx counts
__device__ int   g_urowptr[MAX_N];
__device__ int   g_ucursor[MAX_N];
__device__ int   g_unodes[MAX_N];    // CSR payload for user_idx
__device__ int   g_bsums[MAX_BLKS + 1];
__device__ __align__(8) int2 g_erec[MAX_E];  // {src, norm bits}

// ---------------------------------------------------------------------------
__global__ void k_zero_graph(int N) {
    int i = blockIdx.x * blockDim.x + threadIdx.x;
    if (i < N) { g_hist[i] = 0; g_cursor[i] = 0; g_uhist[i] = 0; g_ucursor[i] = 0; }
}

__global__ void k_hist(const int* __restrict__ dst, int E) {
    int e = blockIdx.x * blockDim.x + threadIdx.x;
    if (e < E) atomicAdd(&g_hist[dst[e]], 1);
}

__global__ void k_uhist(const int* __restrict__ uidx, int N) {
    int i = blockIdx.x * blockDim.x + threadIdx.x;
    if (i < N) atomicAdd(&g_uhist[uidx[i]], 1);
}

// dis = (deg+1)^{-1/2}  (self-loop included)
__global__ void k_dis(int N) {
    int i = blockIdx.x * blockDim.x + threadIdx.x;
    if (i < N) g_dis[i] = rsqrtf((float)(g_hist[i] + 1));
}

// ---- hierarchical exclusive scan: which==0 -> hist/rowptr, 1 -> uhist/urowptr
__global__ void __launch_bounds__(SCAN_TILE) k_scan_local(int which, int N) {
    __shared__ int sh[SCAN_TILE];
    const int* in = which ? g_uhist : g_hist;
    int* outp     = which ? g_urowptr : g_rowptr;
    int tid = threadIdx.x;
    int i = blockIdx.x * SCAN_TILE + tid;
    int v = (i < N) ? in[i] : 0;
    sh[tid] = v;
    __syncthreads();
    for (int off = 1; off < SCAN_TILE; off <<= 1) {
        int t = (tid >= off) ? sh[tid - off] : 0;
        __syncthreads();
        sh[tid] += t;
        __syncthreads();
    }
    if (i < N) outp[i] = sh[tid] - v;
    if (tid == SCAN_TILE - 1) g_bsums[blockIdx.x] = sh[tid];
}

__global__ void k_scan_sums(int nblk) {
    if (threadIdx.x == 0 && blockIdx.x == 0) {
        int acc = 0;
        for (int b = 0; b < nblk; ++b) { int t = g_bsums[b]; g_bsums[b] = acc; acc += t; }
    }
}

__global__ void __launch_bounds__(SCAN_TILE) k_scan_add(int which, int N) {
    int* outp = which ? g_urowptr : g_rowptr;
    int i = blockIdx.x * SCAN_TILE + threadIdx.x;
    if (i < N) outp[i] += g_bsums[blockIdx.x];
}

// scatter edges: record {src, dis[src]*dis[dst]} at CSR slot of dst
__global__ void k_scatter(const int* __restrict__ src,
                          const int* __restrict__ dst, int E) {
    int e = blockIdx.x * blockDim.x + threadIdx.x;
    if (e >= E) return;
    int s = src[e];
    int d = dst[e];
    int pos = g_rowptr[d] + atomicAdd(&g_cursor[d], 1);
    g_erec[pos] = make_int2(s, __float_as_int(g_dis[s] * g_dis[d]));
}

__global__ void k_uscatter(const int* __restrict__ uidx, int N) {
    int i = blockIdx.x * blockDim.x + threadIdx.x;
    if (i >= N) return;
    int u = uidx[i];
    int pos = g_urowptr[u] + atomicAdd(&g_ucursor[u], 1);
    g_unodes[pos] = i;
}

// ---------------------------------------------------------------------------
// Gather aggregation: warp per dst node, lane owns cols {2*lane, 2*lane+1}
// (float2). Edge records read cooperatively (32/warp, coalesced) and
// shuffle-broadcast. Reads g_bufA, writes g_bufB.
// ---------------------------------------------------------------------------
__global__ void __launch_bounds__(256) k_aggr(const float* __restrict__ bias,
                                              int N, int do_relu) {
    int d = (blockIdx.x * blockDim.x + threadIdx.x) >> 5;
    int lane = threadIdx.x & 31;
    if (d >= N) return;

    const float2* __restrict__ h2 = (const float2*)g_bufA;

    float sd = g_dis[d];
    float w = sd * sd;
    float2 hv = h2[(size_t)d * 32 + lane];
    float ax = w * hv.x;
    float ay = w * hv.y;

    int beg = g_rowptr[d];
    int deg = g_hist[d];
    for (int base = 0; base < deg; base += 32) {
        int n = deg - base; if (n > 32) n = 32;
        int2 r = g_erec[beg + base + ((lane < n) ? lane : 0)];
#pragma unroll 4
        for (int j = 0; j < n; ++j) {
            int   s    = __shfl_sync(0xffffffffu, r.x, j);
            float norm = __int_as_float(__shfl_sync(0xffffffffu, r.y, j));
            float2 hs = h2[(size_t)s * 32 + lane];
            ax = fmaf(norm, hs.x, ax);
            ay = fmaf(norm, hs.y, ay);
        }
    }

    float2 bb = ((const float2*)bias)[lane];
    ax += bb.x; ay += bb.y;
    if (do_relu) { ax = fmaxf(ax, 0.f); ay = fmaxf(ay, 0.f); }
    ((float2*)g_bufB)[(size_t)d * 32 + lane] = make_float2(ax, ay);
}

// ---------------------------------------------------------------------------
// scatter-mean as gather: warp per user u; float2 lanes; plain store to d_out.
// ---------------------------------------------------------------------------
__global__ void __launch_bounds__(256) k_umean(float* __restrict__ out, int N) {
    int u = (blockIdx.x * blockDim.x + threadIdx.x) >> 5;
    int lane = threadIdx.x & 31;
    if (u >= N) return;
    const float2* __restrict__ h2 = (const float2*)g_bufB;
    int cnt = g_uhist[u];
    float ax = 0.f, ay = 0.f;
    int beg = g_urowptr[u];
    for (int base = 0; base < cnt; base += 32) {
        int n = cnt - base; if (n > 32) n = 32;
        int node_l = g_unodes[beg + base + ((lane < n) ? lane : 0)];
#pragma unroll 4
        for (int j = 0; j < n; ++j) {
            int node = __shfl_sync(0xffffffffu, node_l, j);
            float2 hs = h2[(size_t)node * 32 + lane];
            ax += hs.x; ay += hs.y;
        }
    }
    float inv = (cnt > 0) ? 1.0f / (float)cnt : 0.f;
    ((float2*)out)[(size_t)u * 32 + lane] = make_float2(ax * inv, ay * inv);
}

// ---------------------------------------------------------------------------
// GEMM: g_bufA[N][64] = A[N][K] @ W[K][64].  in_sel: 0 -> external x, 1 -> g_bufB
// 128x64 block tile, 8x4 per-thread register tile (1.5 B LDS per FMA -> under
// the 128 B/cyc smem crossbar limit, so FFMA issue is unthrottled).
// ---------------------------------------------------------------------------
template <int K>
__global__ void __launch_bounds__(256) gemm_kernel(const float* __restrict__ Ax,
                                                   const float* __restrict__ W,
                                                   int in_sel, int N) {
    const float* __restrict__ A = in_sel ? (const float*)g_bufB : Ax;
    __shared__ float Ws[K][64];        // 32 KB (K=128) / 16 KB (K=64)
    __shared__ float xs[128][33];      // 128 rows x 32-k chunk, padded

    int tid = threadIdx.x;
    for (int i = tid; i < K * 64; i += 256) Ws[i >> 6][i & 63] = W[i];

    int row0 = blockIdx.x * 128;
    int tx = tid & 15;                  // col group: 4 cols
    int ty = tid >> 4;                  // row group: 8 rows

    float acc[8][4];
#pragma unroll
    for (int i = 0; i < 8; ++i)
#pragma unroll
        for (int j = 0; j < 4; ++j) acc[i][j] = 0.f;

    for (int k0 = 0; k0 < K; k0 += 32) {
        __syncthreads();
#pragma unroll
        for (int it = 0; it < 4; ++it) {
            int r  = (tid >> 3) + it * 32;   // 0..127
            int kk = (tid & 7) * 4;          // 0..28
            int row = row0 + r;
            float4 v = make_float4(0.f, 0.f, 0.f, 0.f);
            if (row < N)
                v = *(const float4*)(A + (size_t)row * K + k0 + kk);
            xs[r][kk + 0] = v.x; xs[r][kk + 1] = v.y;
            xs[r][kk + 2] = v.z; xs[r][kk + 3] = v.w;
        }
        __syncthreads();
#pragma unroll
        for (int k = 0; k < 32; ++k) {
            float4 wv = *(const float4*)&Ws[k0 + k][tx * 4];
            float a[8];
#pragma unroll
            for (int i = 0; i < 8; ++i) a[i] = xs[ty * 8 + i][k];
#pragma unroll
            for (int i = 0; i < 8; ++i) {
                acc[i][0] = fmaf(a[i], wv.x, acc[i][0]);
                acc[i][1] = fmaf(a[i], wv.y, acc[i][1]);
                acc[i][2] = fmaf(a[i], wv.z, acc[i][2]);
                acc[i][3] = fmaf(a[i], wv.w, acc[i][3]);
            }
        }
    }
#pragma unroll
    for (int i = 0; i < 8; ++i) {
        int row = row0 + ty * 8 + i;
        if (row < N)
            *(float4*)(&g_bufA[(size_t)row * 64 + tx * 4]) =
                make_float4(acc[i][0], acc[i][1], acc[i][2], acc[i][3]);
    }
}

// ---------------------------------------------------------------------------
static inline int cdiv(int a, int b) { return (a + b - 1) / b; }

extern "C" void kernel_launch(void* const* d_in, const int* in_sizes, int n_in,
                              void* d_out, int out_size) {
    const float* x    = (const float*)d_in[0];
    const int*   ei   = (const int*)d_in[1];      // int32 per harness dtype contract
    const int*   uidx = (const int*)d_in[2];
    const float* W1   = (const float*)d_in[3];
    const float* b1   = (const float*)d_in[4];
    const float* W2   = (const float*)d_in[5];
    const float* b2   = (const float*)d_in[6];
    float* out = (float*)d_out;

    const int N = in_sizes[2];
    const int E = in_sizes[1] / 2;
    const int* src = ei;
    const int* dst = ei + E;

    const int TB = 256;
    const int nblk = cdiv(N, SCAN_TILE);

    // ---- CSR build; gemm1 placed at launch slot 4 to land in the ncu window
    k_zero_graph<<<cdiv(N, TB), TB>>>(N);
    k_hist<<<cdiv(E, TB), TB>>>(dst, E);
    k_uhist<<<cdiv(N, TB), TB>>>(uidx, N);
    gemm_kernel<128><<<cdiv(N, 128), 256>>>(x, W1, 0, N);   // x -> bufA
    k_dis<<<cdiv(N, TB), TB>>>(N);
    k_scan_local<<<nblk, SCAN_TILE>>>(0, N);
    k_scan_sums<<<1, 32>>>(nblk);
    k_scan_add<<<nblk, SCAN_TILE>>>(0, N);
    k_scan_local<<<nblk, SCAN_TILE>>>(1, N);
    k_scan_sums<<<1, 32>>>(nblk);
    k_scan_add<<<nblk, SCAN_TILE>>>(1, N);
    k_scatter<<<cdiv(E, TB), TB>>>(src, dst, E);
    k_uscatter<<<cdiv(N, TB), TB>>>(uidx, N);

    // ---- Layer 1 aggregate: bufA -> bufB (+b1, relu)
    k_aggr<<<cdiv(N * 32, TB), TB>>>(b1, N, 1);

    // ---- Layer 2: gemm (bufB -> bufA), aggregate (bufA -> bufB, +b2)
    gemm_kernel<64><<<cdiv(N, 128), 256>>>(x, W2, 1, N);
    k_aggr<<<cdiv(N * 32, TB), TB>>>(b2, N, 0);

    // ---- scatter_mean via gather (bufB -> out)
    k_umean<<<cdiv(N * 32, TB), TB>>>(out, N);
}

// round 7
// speedup vs baseline: 1.0784x; 1.0784x over previous
#include <cuda_runtime.h>
#include <cuda_bf16.h>
#include <cstdint>

#define MAX_N 100000
#define MAX_E 1600000
#define HID   64
#define SCAN_TILE 1024
#define MAX_BLKS  ((MAX_N + SCAN_TILE - 1) / SCAN_TILE)

// Scratch: __device__ globals, referenced directly by symbol in device code.
__device__ __align__(16) float g_bufA[MAX_N * HID];
__device__ __align__(16) float g_bufB[MAX_N * HID];
__device__ float g_dis[MAX_N];
__device__ int   g_hist[MAX_N];      // edge in-degree (no self-loop)
__device__ int   g_rowptr[MAX_N];
__device__ int   g_cursor[MAX_N];
__device__ int   g_uhist[MAX_N];     // user_idx counts
__device__ int   g_urowptr[MAX_N];
__device__ int   g_ucursor[MAX_N];
__device__ int   g_unodes[MAX_N];    // CSR payload for user_idx
__device__ int   g_bsums[2 * MAX_BLKS + 2];
__device__ __align__(8) int2 g_erec[MAX_E];  // {src, norm bits}

// ---- packed f32x2 helpers (Blackwell; ptxas never auto-fuses these) -------
__device__ __forceinline__ unsigned long long ffma2(unsigned long long a,
                                                    unsigned long long b,
                                                    unsigned long long c) {
    unsigned long long d;
    asm("fma.rn.f32x2 %0, %1, %2, %3;" : "=l"(d) : "l"(a), "l"(b), "l"(c));
    return d;
}
__device__ __forceinline__ unsigned long long pack2(float lo, float hi) {
    unsigned long long d;
    asm("mov.b64 %0, {%1, %2};" : "=l"(d) : "f"(lo), "f"(hi));
    return d;
}
__device__ __forceinline__ void unpack2(unsigned long long v, float& lo, float& hi) {
    asm("mov.b64 {%0, %1}, %2;" : "=f"(lo), "=f"(hi) : "l"(v));
}

// ---------------------------------------------------------------------------
__global__ void k_zero_graph(int N) {
    int i = blockIdx.x * blockDim.x + threadIdx.x;
    if (i < N) { g_hist[i] = 0; g_cursor[i] = 0; g_uhist[i] = 0; g_ucursor[i] = 0; }
}

// fused: edge-dst histogram + user_idx histogram
__global__ void k_histboth(const int* __restrict__ dst, const int* __restrict__ uidx,
                           int E, int N) {
    int i = blockIdx.x * blockDim.x + threadIdx.x;
    if (i < E)          atomicAdd(&g_hist[dst[i]], 1);
    else if (i < E + N) atomicAdd(&g_uhist[uidx[i - E]], 1);
}

// fused hierarchical scan, both CSRs in one grid; dis folded into which==0 pass
__global__ void __launch_bounds__(SCAN_TILE) k_scan_local(int nblk, int N) {
    __shared__ int sh[SCAN_TILE];
    int which = (blockIdx.x >= nblk) ? 1 : 0;
    int blk = blockIdx.x - which * nblk;
    const int* in = which ? g_uhist : g_hist;
    int* outp     = which ? g_urowptr : g_rowptr;
    int tid = threadIdx.x;
    int i = blk * SCAN_TILE + tid;
    int v = (i < N) ? in[i] : 0;
    sh[tid] = v;
    __syncthreads();
    for (int off = 1; off < SCAN_TILE; off <<= 1) {
        int t = (tid >= off) ? sh[tid - off] : 0;
        __syncthreads();
        sh[tid] += t;
        __syncthreads();
    }
    if (i < N) {
        outp[i] = sh[tid] - v;
        if (!which) g_dis[i] = rsqrtf((float)(v + 1));   // deg+1 (self-loop)
    }
    if (tid == SCAN_TILE - 1) g_bsums[blockIdx.x] = sh[tid];
}

__global__ void k_scan_sums(int nblk) {
    int t = threadIdx.x;
    if (t < 2) {
        int acc = 0;
        for (int b = t * nblk; b < (t + 1) * nblk; ++b) {
            int v = g_bsums[b]; g_bsums[b] = acc; acc += v;
        }
    }
}

__global__ void __launch_bounds__(SCAN_TILE) k_scan_add(int nblk, int N) {
    int which = (blockIdx.x >= nblk) ? 1 : 0;
    int blk = blockIdx.x - which * nblk;
    int* outp = which ? g_urowptr : g_rowptr;
    int i = blk * SCAN_TILE + threadIdx.x;
    if (i < N) outp[i] += g_bsums[blockIdx.x];
}

// fused: edge scatter + user scatter
__global__ void k_scatterboth(const int* __restrict__ src, const int* __restrict__ dst,
                              const int* __restrict__ uidx, int E, int N) {
    int i = blockIdx.x * blockDim.x + threadIdx.x;
    if (i < E) {
        int s = src[i];
        int d = dst[i];
        int pos = g_rowptr[d] + atomicAdd(&g_cursor[d], 1);
        g_erec[pos] = make_int2(s, __float_as_int(g_dis[s] * g_dis[d]));
    } else if (i < E + N) {
        int n = i - E;
        int u = uidx[n];
        int pos = g_urowptr[u] + atomicAdd(&g_ucursor[u], 1);
        g_unodes[pos] = n;
    }
}

// ---------------------------------------------------------------------------
// Gather aggregation: warp per dst node, lane owns cols {2*lane, 2*lane+1}
// (float2). Edge records read cooperatively (32/warp, coalesced) and
// shuffle-broadcast. Reads g_bufA, writes g_bufB.
// ---------------------------------------------------------------------------
__global__ void __launch_bounds__(256) k_aggr(const float* __restrict__ bias,
                                              int N, int do_relu) {
    int d = (blockIdx.x * blockDim.x + threadIdx.x) >> 5;
    int lane = threadIdx.x & 31;
    if (d >= N) return;

    const float2* __restrict__ h2 = (const float2*)g_bufA;

    float sd = g_dis[d];
    float w = sd * sd;
    float2 hv = h2[(size_t)d * 32 + lane];
    float ax = w * hv.x;
    float ay = w * hv.y;

    int beg = g_rowptr[d];
    int deg = g_hist[d];
    for (int base = 0; base < deg; base += 32) {
        int n = deg - base; if (n > 32) n = 32;
        int2 r = g_erec[beg + base + ((lane < n) ? lane : 0)];
#pragma unroll 4
        for (int j = 0; j < n; ++j) {
            int   s    = __shfl_sync(0xffffffffu, r.x, j);
            float norm = __int_as_float(__shfl_sync(0xffffffffu, r.y, j));
            float2 hs = h2[(size_t)s * 32 + lane];
            ax = fmaf(norm, hs.x, ax);
            ay = fmaf(norm, hs.y, ay);
        }
    }

    float2 bb = ((const float2*)bias)[lane];
    ax += bb.x; ay += bb.y;
    if (do_relu) { ax = fmaxf(ax, 0.f); ay = fmaxf(ay, 0.f); }
    ((float2*)g_bufB)[(size_t)d * 32 + lane] = make_float2(ax, ay);
}

// ---------------------------------------------------------------------------
// scatter-mean as gather: warp per user u; float2 lanes; plain store to d_out.
// ---------------------------------------------------------------------------
__global__ void __launch_bounds__(256) k_umean(float* __restrict__ out, int N) {
    int u = (blockIdx.x * blockDim.x + threadIdx.x) >> 5;
    int lane = threadIdx.x & 31;
    if (u >= N) return;
    const float2* __restrict__ h2 = (const float2*)g_bufB;
    int cnt = g_uhist[u];
    float ax = 0.f, ay = 0.f;
    int beg = g_urowptr[u];
    for (int base = 0; base < cnt; base += 32) {
        int n = cnt - base; if (n > 32) n = 32;
        int node_l = g_unodes[beg + base + ((lane < n) ? lane : 0)];
#pragma unroll 4
        for (int j = 0; j < n; ++j) {
            int node = __shfl_sync(0xffffffffu, node_l, j);
            float2 hs = h2[(size_t)node * 32 + lane];
            ax += hs.x; ay += hs.y;
        }
    }
    float inv = (cnt > 0) ? 1.0f / (float)cnt : 0.f;
    ((float2*)out)[(size_t)u * 32 + lane] = make_float2(ax * inv, ay * inv);
}

// ---------------------------------------------------------------------------
// GEMM via packed FFMA2: g_bufA[N][64] = A[N][K] @ W[K][64].
// 128x64 block tile, 256 threads, per-thread 8 rows x 4 cols held as
// 4 row-pair x 4 col packed f32x2 accumulators. A staged k-major in smem so
// a row pair is one LDS.64 (2 distinct addrs/warp -> broadcast).
// ---------------------------------------------------------------------------
template <int K>
__global__ void __launch_bounds__(256) gemm_kernel(const float* __restrict__ Ax,
                                                   const float* __restrict__ W,
                                                   int in_sel, int N) {
    const float* __restrict__ A = in_sel ? (const float*)g_bufB : Ax;
    __shared__ float Ws[K][64];                 // 32 KB (K=128) / 16 KB (K=64)
    __shared__ __align__(16) float xs[32][134]; // k-major A chunk, padded

    int tid = threadIdx.x;
    for (int i = tid; i < K * 64; i += 256) Ws[i >> 6][i & 63] = W[i];

    int row0 = blockIdx.x * 128;
    int tx = tid & 15;                  // col group: 4 cols
    int ty = tid >> 4;                  // row group: 8 rows (4 pairs)

    unsigned long long acc[4][4];       // [row pair][col]
#pragma unroll
    for (int i = 0; i < 4; ++i)
#pragma unroll
        for (int j = 0; j < 4; ++j) acc[i][j] = 0ULL;

    for (int k0 = 0; k0 < K; k0 += 32) {
        __syncthreads();
#pragma unroll
        for (int it = 0; it < 4; ++it) {
            int r  = (tid >> 3) + it * 32;   // 0..127
            int kk = (tid & 7) * 4;          // 0..28
            int row = row0 + r;
            float4 v = make_float4(0.f, 0.f, 0.f, 0.f);
            if (row < N)
                v = *(const float4*)(A + (size_t)row * K + k0 + kk);
            xs[kk + 0][r] = v.x; xs[kk + 1][r] = v.y;
            xs[kk + 2][r] = v.z; xs[kk + 3][r] = v.w;
        }
        __syncthreads();
#pragma unroll
        for (int k = 0; k < 32; ++k) {
            float4 wv = *(const float4*)&Ws[k0 + k][tx * 4];
            unsigned long long wd[4];
            wd[0] = pack2(wv.x, wv.x); wd[1] = pack2(wv.y, wv.y);
            wd[2] = pack2(wv.z, wv.z); wd[3] = pack2(wv.w, wv.w);
            unsigned long long ap[4];
#pragma unroll
            for (int i = 0; i < 4; ++i)
                ap[i] = *(const unsigned long long*)&xs[k][ty * 8 + 2 * i];
#pragma unroll
            for (int i = 0; i < 4; ++i) {
                acc[i][0] = ffma2(ap[i], wd[0], acc[i][0]);
                acc[i][1] = ffma2(ap[i], wd[1], acc[i][1]);
                acc[i][2] = ffma2(ap[i], wd[2], acc[i][2]);
                acc[i][3] = ffma2(ap[i], wd[3], acc[i][3]);
            }
        }
    }
#pragma unroll
    for (int i = 0; i < 4; ++i) {
        float lo0, hi0, lo1, hi1, lo2, hi2, lo3, hi3;
        unpack2(acc[i][0], lo0, hi0);
        unpack2(acc[i][1], lo1, hi1);
        unpack2(acc[i][2], lo2, hi2);
        unpack2(acc[i][3], lo3, hi3);
        int rowA = row0 + ty * 8 + 2 * i;
        int rowB = rowA + 1;
        if (rowA < N)
            *(float4*)(&g_bufA[(size_t)rowA * 64 + tx * 4]) =
                make_float4(lo0, lo1, lo2, lo3);
        if (rowB < N)
            *(float4*)(&g_bufA[(size_t)rowB * 64 + tx * 4]) =
                make_float4(hi0, hi1, hi2, hi3);
    }
}

// ---------------------------------------------------------------------------
static inline int cdiv(int a, int b) { return (a + b - 1) / b; }

extern "C" void kernel_launch(void* const* d_in, const int* in_sizes, int n_in,
                              void* d_out, int out_size) {
    const float* x    = (const float*)d_in[0];
    const int*   ei   = (const int*)d_in[1];      // int32 per harness dtype contract
    const int*   uidx = (const int*)d_in[2];
    const float* W1   = (const float*)d_in[3];
    const float* b1   = (const float*)d_in[4];
    const float* W2   = (const float*)d_in[5];
    const float* b2   = (const float*)d_in[6];
    float* out = (float*)d_out;

    const int N = in_sizes[2];
    const int E = in_sizes[1] / 2;
    const int* src = ei;
    const int* dst = ei + E;

    const int TB = 256;
    const int nblk = cdiv(N, SCAN_TILE);

    // 1-3: graph prep
    k_zero_graph<<<cdiv(N, TB), TB>>>(N);
    k_histboth<<<cdiv(E + N, TB), TB>>>(dst, uidx, E, N);
    k_scan_local<<<2 * nblk, SCAN_TILE>>>(nblk, N);
    // 4: gemm1 (x -> bufA) — kept at slot 4 for the ncu window
    gemm_kernel<128><<<cdiv(N, 128), 256>>>(x, W1, 0, N);
    // 5-7: finish CSRs
    k_scan_sums<<<1, 32>>>(nblk);
    k_scan_add<<<2 * nblk, SCAN_TILE>>>(nblk, N);
    k_scatterboth<<<cdiv(E + N, TB), TB>>>(src, dst, uidx, E, N);
    // 8: layer-1 aggregate (bufA -> bufB, +b1, relu)
    k_aggr<<<cdiv(N * 32, TB), TB>>>(b1, N, 1);
    // 9-10: layer 2
    gemm_kernel<64><<<cdiv(N, 128), 256>>>(x, W2, 1, N);   // bufB -> bufA
    k_aggr<<<cdiv(N * 32, TB), TB>>>(b2, N, 0);            // bufA -> bufB
    // 11: scatter-mean (bufB -> out)
    k_umean<<<cdiv(N * 32, TB), TB>>>(out, N);
}